// round 4
// baseline (speedup 1.0000x reference)
#include <cuda_runtime.h>
#include <cuda_bf16.h>

#define N_NODES 50000
#define E_EDGES 800000
#define D 128
#define SCAN_T 1024

// Scratch (device globals — no allocation allowed)
__device__ int   g_cnt[N_NODES];        // dst-degree histogram (excl. self-loop)
__device__ int   g_rowptr[N_NODES + 1]; // CSR row offsets (by dst)
__device__ int   g_cursor[N_NODES];     // scatter cursors
__device__ int   g_srcs[E_EDGES];       // CSR column indices (src per edge)
__device__ float g_dinv[N_NODES];
__device__ float g_y[(size_t)N_NODES * D]; // y = dinv[i] * (x @ W^T)[i]

// ---------------------------------------------------------------------------
__global__ void k_zero() {
    int i = blockIdx.x * blockDim.x + threadIdx.x;
    if (i < N_NODES) g_cnt[i] = 0;
}

__global__ void k_hist(const int* __restrict__ dst) {
    int e = blockIdx.x * blockDim.x + threadIdx.x;
    if (e < E_EDGES) atomicAdd(&g_cnt[dst[e]], 1);
}

// Single-block exclusive scan over 50k counts; also derives dinv and cursors.
__global__ __launch_bounds__(SCAN_T)
void k_scan() {
    __shared__ int sums[SCAN_T];
    const int CH = (N_NODES + SCAN_T - 1) / SCAN_T;  // 49
    int t = threadIdx.x;
    int base = t * CH;

    int local = 0;
    for (int i = 0; i < CH; i++) {
        int idx = base + i;
        if (idx < N_NODES) local += g_cnt[idx];
    }
    sums[t] = local;
    __syncthreads();

    // Hillis-Steele inclusive scan (read phase / write phase separated by syncs)
    for (int off = 1; off < SCAN_T; off <<= 1) {
        int v   = sums[t];
        int add = (t >= off) ? sums[t - off] : 0;
        __syncthreads();
        sums[t] = v + add;
        __syncthreads();
    }
    int prefix = (t == 0) ? 0 : sums[t - 1];

    for (int i = 0; i < CH; i++) {
        int idx = base + i;
        if (idx < N_NODES) {
            g_rowptr[idx] = prefix;
            g_cursor[idx] = prefix;
            int c = g_cnt[idx];
            g_dinv[idx] = rsqrtf((float)(c + 1));  // +1 self-loop
            prefix += c;
        }
    }
    if (t == SCAN_T - 1) g_rowptr[N_NODES] = prefix;
}

__global__ void k_scatter(const int* __restrict__ src, const int* __restrict__ dst) {
    int e = blockIdx.x * blockDim.x + threadIdx.x;
    if (e < E_EDGES) {
        int pos = atomicAdd(&g_cursor[dst[e]], 1);
        g_srcs[pos] = src[e];
    }
}

// ---------------------------------------------------------------------------
// SGEMM y = dinv[i] * (x @ W^T)[i]. Tile BM=128, BN=128, BK=8, 256 thr, 8x8.
__global__ __launch_bounds__(256, 2)
void k_gemm(const float* __restrict__ x, const float* __restrict__ W) {
    __shared__ float As[8][132];
    __shared__ float Bs[8][132];

    const int tid = threadIdx.x;
    const int m0  = blockIdx.x * 128;
    const int tx  = tid & 15;
    const int ty  = tid >> 4;

    const int lr = tid >> 1;        // 0..127
    const int kg = (tid & 1) * 4;   // 0 or 4

    float acc[8][8];
#pragma unroll
    for (int i = 0; i < 8; i++)
#pragma unroll
        for (int j = 0; j < 8; j++) acc[i][j] = 0.0f;

    for (int k0 = 0; k0 < D; k0 += 8) {
        float4 av = make_float4(0.f, 0.f, 0.f, 0.f);
        int gr = m0 + lr;
        if (gr < N_NODES) av = *(const float4*)(x + (size_t)gr * D + k0 + kg);
        As[kg + 0][lr] = av.x; As[kg + 1][lr] = av.y;
        As[kg + 2][lr] = av.z; As[kg + 3][lr] = av.w;

        float4 bv = *(const float4*)(W + (size_t)lr * D + k0 + kg);
        Bs[kg + 0][lr] = bv.x; Bs[kg + 1][lr] = bv.y;
        Bs[kg + 2][lr] = bv.z; Bs[kg + 3][lr] = bv.w;

        __syncthreads();

#pragma unroll
        for (int k = 0; k < 8; k++) {
            float ar[8], br[8];
#pragma unroll
            for (int i = 0; i < 8; i++) ar[i] = As[k][ty * 8 + i];
#pragma unroll
            for (int j = 0; j < 8; j++) br[j] = Bs[k][tx * 8 + j];
#pragma unroll
            for (int i = 0; i < 8; i++)
#pragma unroll
                for (int j = 0; j < 8; j++) acc[i][j] += ar[i] * br[j];
        }
        __syncthreads();
    }

#pragma unroll
    for (int i = 0; i < 8; i++) {
        int row = m0 + ty * 8 + i;
        if (row >= N_NODES) continue;
        float di = g_dinv[row];
#pragma unroll
        for (int jj = 0; jj < 2; jj++) {
            int col = tx * 8 + jj * 4;
            float4 v = make_float4(acc[i][jj*4+0] * di, acc[i][jj*4+1] * di,
                                   acc[i][jj*4+2] * di, acc[i][jj*4+3] * di);
            *(float4*)(g_y + (size_t)row * D + col) = v;
        }
    }
}

// ---------------------------------------------------------------------------
// Aggregation: warp per dst node. out[d] = dinv[d]*(sum_{s in N(d)} y[s] + y[d]) + b
// 4-way unrolled independent gathers for MLP.
__global__ __launch_bounds__(256)
void k_agg(const float* __restrict__ b, float* __restrict__ out) {
    int w    = (blockIdx.x * blockDim.x + threadIdx.x) >> 5;
    int lane = threadIdx.x & 31;
    if (w >= N_NODES) return;

    int beg = g_rowptr[w];
    int end = g_rowptr[w + 1];
    int off = lane * 4;

    // self-loop term
    float4 a0 = *(const float4*)(g_y + (size_t)w * D + off);
    float4 a1 = make_float4(0.f, 0.f, 0.f, 0.f);
    float4 a2 = a1, a3 = a1;

    int j = beg;
    for (; j + 4 <= end; j += 4) {
        int s0 = __ldg(g_srcs + j);
        int s1 = __ldg(g_srcs + j + 1);
        int s2 = __ldg(g_srcs + j + 2);
        int s3 = __ldg(g_srcs + j + 3);
        float4 v0 = *(const float4*)(g_y + (size_t)s0 * D + off);
        float4 v1 = *(const float4*)(g_y + (size_t)s1 * D + off);
        float4 v2 = *(const float4*)(g_y + (size_t)s2 * D + off);
        float4 v3 = *(const float4*)(g_y + (size_t)s3 * D + off);
        a0.x += v0.x; a0.y += v0.y; a0.z += v0.z; a0.w += v0.w;
        a1.x += v1.x; a1.y += v1.y; a1.z += v1.z; a1.w += v1.w;
        a2.x += v2.x; a2.y += v2.y; a2.z += v2.z; a2.w += v2.w;
        a3.x += v3.x; a3.y += v3.y; a3.z += v3.z; a3.w += v3.w;
    }
    for (; j < end; j++) {
        int s = __ldg(g_srcs + j);
        float4 v = *(const float4*)(g_y + (size_t)s * D + off);
        a0.x += v.x; a0.y += v.y; a0.z += v.z; a0.w += v.w;
    }

    a0.x += a1.x + a2.x + a3.x;
    a0.y += a1.y + a2.y + a3.y;
    a0.z += a1.z + a2.z + a3.z;
    a0.w += a1.w + a2.w + a3.w;

    float di = g_dinv[w];
    float4 bb = *(const float4*)(b + off);
    float4 o = make_float4(a0.x * di + bb.x, a0.y * di + bb.y,
                           a0.z * di + bb.z, a0.w * di + bb.w);
    *(float4*)(out + (size_t)w * D + off) = o;
}

// ---------------------------------------------------------------------------
extern "C" void kernel_launch(void* const* d_in, const int* in_sizes, int n_in,
                              void* d_out, int out_size) {
    const float* x  = (const float*)d_in[0];
    const int*   ei = (const int*)d_in[1];   // [2, E]: row 0 = src, row 1 = dst
    const float* W  = (const float*)d_in[2];
    const float* b  = (const float*)d_in[3];
    float* out = (float*)d_out;

    const int* src = ei;
    const int* dst = ei + E_EDGES;

    k_zero<<<(N_NODES + 255) / 256, 256>>>();
    k_hist<<<(E_EDGES + 255) / 256, 256>>>(dst);
    k_scan<<<1, SCAN_T>>>();
    k_scatter<<<(E_EDGES + 255) / 256, 256>>>(src, dst);
    k_gemm<<<(N_NODES + 127) / 128, 256>>>(x, W);

    long long total = (long long)N_NODES * 32;
    int blocks = (int)((total + 255) / 256);
    k_agg<<<blocks, 256>>>(b, out);
}

// round 9
// speedup vs baseline: 1.4478x; 1.4478x over previous
#include <cuda_runtime.h>
#include <cuda_fp16.h>
#include <cuda_bf16.h>
#include <cstdint>
#include <cstddef>

#define N_NODES 50000
#define E_EDGES 800000
#define D 128

// Scratch (device globals -- no allocation allowed)
__device__ float g_deg[N_NODES];
__device__ float g_dinv[N_NODES];
__device__ float g_y[(size_t)N_NODES * D];   // y = dinv[i] * (x @ W^T)[i]

// ---------------------------------------------------------------------------
__global__ void k_init_deg() {
    int i = blockIdx.x * blockDim.x + threadIdx.x;
    if (i < N_NODES) g_deg[i] = 1.0f;   // self-loop
}

__global__ void k_count(const int* __restrict__ dst) {
    int e = blockIdx.x * blockDim.x + threadIdx.x;
    if (e < E_EDGES) atomicAdd(&g_deg[dst[e]], 1.0f);
}

__global__ void k_dinv() {
    int i = blockIdx.x * blockDim.x + threadIdx.x;
    if (i < N_NODES) g_dinv[i] = rsqrtf(g_deg[i]);
}

// ---------------------------------------------------------------------------
// Tensor-core GEMM, fp16 2-term split (Markidis) for fp32-grade precision.
// Block: 128 rows x full N=128 x K=128. 8 warps; warp wm owns rows wm*16..+15.
// smem row stride 136 halves (272B) keeps ldmatrix conflict-free.

#define SM_STRIDE 136
#define SM_ARR (128 * SM_STRIDE)
#define GEMM_SMEM_BYTES (4 * SM_ARR * 2)

struct Frag4 { uint32_t r[4]; };

__device__ __forceinline__ void ldsm4(Frag4& f, uint32_t addr) {
    asm volatile(
        "ldmatrix.sync.aligned.m8n8.x4.shared.b16 {%0,%1,%2,%3}, [%4];"
        : "=r"(f.r[0]), "=r"(f.r[1]), "=r"(f.r[2]), "=r"(f.r[3])
        : "r"(addr));
}

__device__ __forceinline__ void mma16816(float* c, const Frag4& a,
                                         uint32_t b0, uint32_t b1) {
    asm volatile(
        "mma.sync.aligned.m16n8k16.row.col.f32.f16.f16.f32 "
        "{%0,%1,%2,%3}, {%4,%5,%6,%7}, {%8,%9}, {%0,%1,%2,%3};"
        : "+f"(c[0]), "+f"(c[1]), "+f"(c[2]), "+f"(c[3])
        : "r"(a.r[0]), "r"(a.r[1]), "r"(a.r[2]), "r"(a.r[3]),
          "r"(b0), "r"(b1));
}

__global__ __launch_bounds__(256)
void k_gemm_mma(const float* __restrict__ x, const float* __restrict__ W,
                const float* __restrict__ b, float* __restrict__ out) {
    extern __shared__ __half sm[];
    __half* Ws_hi = sm;
    __half* Ws_lo = sm + SM_ARR;
    __half* Xs_hi = sm + 2 * SM_ARR;
    __half* Xs_lo = sm + 3 * SM_ARR;

    const int tid  = threadIdx.x;
    const int lane = tid & 31;
    const int wm   = tid >> 5;
    const int m0   = blockIdx.x * 128;

    // Stage W split into hi/lo halves
    for (int i = tid; i < 128 * 128; i += 256) {
        int r = i >> 7;
        int c = i & 127;
        float v   = W[i];
        __half hi = __float2half_rn(v);
        __half lo = __float2half_rn(v - __half2float(hi));
        Ws_hi[r * SM_STRIDE + c] = hi;
        Ws_lo[r * SM_STRIDE + c] = lo;
    }
    // Stage x tile split into hi/lo, zero-pad tail rows
    for (int i = tid; i < 128 * 128; i += 256) {
        int r = i >> 7;
        int c = i & 127;
        int gr = m0 + r;
        float v = 0.0f;
        if (gr < N_NODES) v = x[(size_t)gr * D + c];
        __half hi = __float2half_rn(v);
        __half lo = __float2half_rn(v - __half2float(hi));
        Xs_hi[r * SM_STRIDE + c] = hi;
        Xs_lo[r * SM_STRIDE + c] = lo;
    }
    __syncthreads();

    // ldmatrix lane addressing (element offsets in halves)
    const int aRow = wm * 16 + (lane & 7) + ((lane >> 3) & 1) * 8;
    const int aCol = (lane >> 4) * 8;
    const int bRow = ((lane >> 4) & 1) * 8 + (lane & 7);
    const int bCol = ((lane >> 3) & 1) * 8;

    const uint32_t xs_hi_b = (uint32_t)__cvta_generic_to_shared(Xs_hi);
    const uint32_t xs_lo_b = (uint32_t)__cvta_generic_to_shared(Xs_lo);
    const uint32_t ws_hi_b = (uint32_t)__cvta_generic_to_shared(Ws_hi);
    const uint32_t ws_lo_b = (uint32_t)__cvta_generic_to_shared(Ws_lo);

    float acc[16][4];
#pragma unroll
    for (int n = 0; n < 16; n++) {
#pragma unroll
        for (int j = 0; j < 4; j++) acc[n][j] = 0.0f;
    }

#pragma unroll
    for (int ks = 0; ks < 8; ks++) {
        const int k0 = ks * 16;
        const uint32_t aoff = (uint32_t)(aRow * SM_STRIDE + k0 + aCol) * 2;
        Frag4 ah, al;
        ldsm4(ah, xs_hi_b + aoff);
        ldsm4(al, xs_lo_b + aoff);

#pragma unroll
        for (int p = 0; p < 8; p++) {
            const uint32_t boff =
                (uint32_t)((p * 16 + bRow) * SM_STRIDE + k0 + bCol) * 2;
            Frag4 bh, bl;
            ldsm4(bh, ws_hi_b + boff);
            ldsm4(bl, ws_lo_b + boff);

            float* c0 = acc[2 * p];
            float* c1 = acc[2 * p + 1];
            // n-tile 2p (B regs 0,1)
            mma16816(c0, ah, bh.r[0], bh.r[1]);
            mma16816(c0, ah, bl.r[0], bl.r[1]);
            mma16816(c0, al, bh.r[0], bh.r[1]);
            // n-tile 2p+1 (B regs 2,3)
            mma16816(c1, ah, bh.r[2], bh.r[3]);
            mma16816(c1, ah, bl.r[2], bl.r[3]);
            mma16816(c1, al, bh.r[2], bh.r[3]);
        }
    }

    // Epilogue: g_y = dinv*xlin ; out = dinv^2*xlin + b
    const int gid  = lane >> 2;
    const int tig  = lane & 3;
    const int row0 = m0 + wm * 16 + gid;
    const int row1 = row0 + 8;
    float di0 = 0.0f;
    float di1 = 0.0f;
    if (row0 < N_NODES) di0 = g_dinv[row0];
    if (row1 < N_NODES) di1 = g_dinv[row1];

#pragma unroll
    for (int nt = 0; nt < 16; nt++) {
        int n = nt * 8 + tig * 2;
        float b0 = b[n];
        float b1 = b[n + 1];
        if (row0 < N_NODES) {
            float y0 = acc[nt][0] * di0;
            float y1 = acc[nt][1] * di0;
            *(float2*)(g_y + (size_t)row0 * D + n) = make_float2(y0, y1);
            float2 o;
            o.x = y0 * di0 + b0;
            o.y = y1 * di0 + b1;
            *(float2*)(out + (size_t)row0 * D + n) = o;
        }
        if (row1 < N_NODES) {
            float y0 = acc[nt][2] * di1;
            float y1 = acc[nt][3] * di1;
            *(float2*)(g_y + (size_t)row1 * D + n) = make_float2(y0, y1);
            float2 o;
            o.x = y0 * di1 + b0;
            o.y = y1 * di1 + b1;
            *(float2*)(out + (size_t)row1 * D + n) = o;
        }
    }
}

// ---------------------------------------------------------------------------
// Edge scatter: one warp per edge; lane handles a float4. y is pre-scaled by
// dinv[src], so msg = dinv[dst] * y[src]. Vector reduction into out[dst].
__global__ __launch_bounds__(256)
void k_edges(const int* __restrict__ src, const int* __restrict__ dst,
             float* __restrict__ out) {
    int w    = (blockIdx.x * blockDim.x + threadIdx.x) >> 5;
    int lane = threadIdx.x & 31;
    if (w >= E_EDGES) return;

    int s = __ldg(src + w);
    int d = __ldg(dst + w);
    float nd = g_dinv[d];

    float4 v = *(const float4*)(g_y + (size_t)s * D + lane * 4);
    float* p = out + (size_t)d * D + lane * 4;
    asm volatile("red.global.add.v4.f32 [%0], {%1, %2, %3, %4};" ::
                 "l"(p),
                 "f"(v.x * nd), "f"(v.y * nd),
                 "f"(v.z * nd), "f"(v.w * nd)
                 : "memory");
}

// ---------------------------------------------------------------------------
extern "C" void kernel_launch(void* const* d_in, const int* in_sizes, int n_in,
                              void* d_out, int out_size) {
    const float* x  = (const float*)d_in[0];
    const int*   ei = (const int*)d_in[1];   // [2, E]: row 0 = src, row 1 = dst
    const float* W  = (const float*)d_in[2];
    const float* b  = (const float*)d_in[3];
    float* out = (float*)d_out;

    const int* src = ei;
    const int* dst = ei + E_EDGES;

    cudaFuncSetAttribute(k_gemm_mma,
                         cudaFuncAttributeMaxDynamicSharedMemorySize,
                         GEMM_SMEM_BYTES);

    k_init_deg<<<(N_NODES + 255) / 256, 256>>>();
    k_count<<<(E_EDGES + 255) / 256, 256>>>(dst);
    k_dinv<<<(N_NODES + 255) / 256, 256>>>();
    k_gemm_mma<<<(N_NODES + 127) / 128, 256, GEMM_SMEM_BYTES>>>(x, W, b, out);

    long long total = (long long)E_EDGES * 32;
    int blocks = (int)((total + 255) / 256);
    k_edges<<<blocks, 256>>>(src, dst, out);
}

// round 12
// speedup vs baseline: 1.6365x; 1.1303x over previous
#include <cuda_runtime.h>
#include <cuda_fp16.h>
#include <cuda_bf16.h>
#include <cstdint>
#include <cstddef>

#define N_NODES 50000
#define E_EDGES 800000
#define D 128

// Scratch (device globals -- no allocation allowed)
__device__ float  g_deg[N_NODES];
__device__ float  g_dinv[N_NODES];
__device__ float  g_y[(size_t)N_NODES * D];     // y = dinv[i] * (x @ W^T)[i]
__device__ __half g_Whi[D * D];
__device__ __half g_Wlo[D * D];

// ---------------------------------------------------------------------------
__global__ void k_init_deg() {
    int i = blockIdx.x * blockDim.x + threadIdx.x;
    if (i < N_NODES) g_deg[i] = 1.0f;   // self-loop
}

__global__ void k_count(const int* __restrict__ dst) {
    int e = blockIdx.x * blockDim.x + threadIdx.x;
    if (e < E_EDGES) atomicAdd(&g_deg[dst[e]], 1.0f);
}

__global__ void k_dinv() {
    int i = blockIdx.x * blockDim.x + threadIdx.x;
    if (i < N_NODES) g_dinv[i] = rsqrtf(g_deg[i]);
}

// Precompute W split (once): Whi = fp16(W), Wlo = fp16(W - Whi)
__global__ void k_prep_w(const float* __restrict__ W) {
    int i = blockIdx.x * blockDim.x + threadIdx.x;
    if (i < D * D) {
        float v   = W[i];
        __half hi = __float2half_rn(v);
        __half lo = __float2half_rn(v - __half2float(hi));
        g_Whi[i] = hi;
        g_Wlo[i] = lo;
    }
}

// ---------------------------------------------------------------------------
// Tensor-core GEMM, fp16 2-term split (Markidis).
// 512 threads = 16 warps. Warp w: m-tile (w&7) -> rows (w&7)*16..+15,
// n-half (w>>3) -> n-tile pairs p in [ (w>>3)*4, +4 ).
// smem row stride 136 halves (272B) keeps ldmatrix conflict-free.

#define SM_STRIDE 136
#define SM_ARR (128 * SM_STRIDE)
#define GEMM_SMEM_BYTES (4 * SM_ARR * 2)

struct Frag4 { uint32_t r[4]; };

__device__ __forceinline__ void ldsm4(Frag4& f, uint32_t addr) {
    asm volatile(
        "ldmatrix.sync.aligned.m8n8.x4.shared.b16 {%0,%1,%2,%3}, [%4];"
        : "=r"(f.r[0]), "=r"(f.r[1]), "=r"(f.r[2]), "=r"(f.r[3])
        : "r"(addr));
}

__device__ __forceinline__ void mma16816(float* c, const Frag4& a,
                                         uint32_t b0, uint32_t b1) {
    asm volatile(
        "mma.sync.aligned.m16n8k16.row.col.f32.f16.f16.f32 "
        "{%0,%1,%2,%3}, {%4,%5,%6,%7}, {%8,%9}, {%0,%1,%2,%3};"
        : "+f"(c[0]), "+f"(c[1]), "+f"(c[2]), "+f"(c[3])
        : "r"(a.r[0]), "r"(a.r[1]), "r"(a.r[2]), "r"(a.r[3]),
          "r"(b0), "r"(b1));
}

__device__ __forceinline__ uint32_t h2bits(__half a, __half b) {
    __half2 h = __halves2half2(a, b);
    return *(uint32_t*)&h;
}

__global__ __launch_bounds__(512)
void k_gemm_mma(const float* __restrict__ x, const float* __restrict__ b,
                float* __restrict__ out) {
    extern __shared__ __half sm[];
    __half* Ws_hi = sm;
    __half* Ws_lo = sm + SM_ARR;
    __half* Xs_hi = sm + 2 * SM_ARR;
    __half* Xs_lo = sm + 3 * SM_ARR;

    const int tid  = threadIdx.x;
    const int lane = tid & 31;
    const int wid  = tid >> 5;        // 0..15
    const int wm   = wid & 7;         // m-tile
    const int wn   = wid >> 3;        // n-half (0/1)
    const int m0   = blockIdx.x * 128;

    // ---- Stage W: pure vector copies from precomputed global hi/lo ----
    // 128 rows x 16 uint4 per row per array.
    for (int i = tid; i < 128 * 16; i += 512) {
        int r  = i >> 4;
        int c  = i & 15;             // uint4 index within row (8 halves each)
        const uint4* shi = (const uint4*)(g_Whi + r * 128 + c * 8);
        const uint4* slo = (const uint4*)(g_Wlo + r * 128 + c * 8);
        *(uint4*)(Ws_hi + r * SM_STRIDE + c * 8) = *shi;
        *(uint4*)(Ws_lo + r * SM_STRIDE + c * 8) = *slo;
    }

    // ---- Stage X: float4 loads, packed half2 stores ----
    // 128 rows x 32 float4 per row.
    for (int i = tid; i < 128 * 32; i += 512) {
        int r  = i >> 5;
        int c4 = i & 31;             // float4 index (4 floats)
        int gr = m0 + r;
        float4 v = make_float4(0.f, 0.f, 0.f, 0.f);
        if (gr < N_NODES) v = *(const float4*)(x + (size_t)gr * D + c4 * 4);

        __half h0 = __float2half_rn(v.x);
        __half h1 = __float2half_rn(v.y);
        __half h2 = __float2half_rn(v.z);
        __half h3 = __float2half_rn(v.w);
        __half l0 = __float2half_rn(v.x - __half2float(h0));
        __half l1 = __float2half_rn(v.y - __half2float(h1));
        __half l2 = __float2half_rn(v.z - __half2float(h2));
        __half l3 = __float2half_rn(v.w - __half2float(h3));

        uint2 hv, lv;
        hv.x = h2bits(h0, h1); hv.y = h2bits(h2, h3);
        lv.x = h2bits(l0, l1); lv.y = h2bits(l2, l3);
        *(uint2*)(Xs_hi + r * SM_STRIDE + c4 * 4) = hv;
        *(uint2*)(Xs_lo + r * SM_STRIDE + c4 * 4) = lv;
    }
    __syncthreads();

    // ldmatrix lane addressing (element offsets in halves)
    const int aRow = wm * 16 + (lane & 7) + ((lane >> 3) & 1) * 8;
    const int aCol = (lane >> 4) * 8;
    const int bRow = ((lane >> 4) & 1) * 8 + (lane & 7);
    const int bCol = ((lane >> 3) & 1) * 8;

    const uint32_t xs_hi_b = (uint32_t)__cvta_generic_to_shared(Xs_hi);
    const uint32_t xs_lo_b = (uint32_t)__cvta_generic_to_shared(Xs_lo);
    const uint32_t ws_hi_b = (uint32_t)__cvta_generic_to_shared(Ws_hi);
    const uint32_t ws_lo_b = (uint32_t)__cvta_generic_to_shared(Ws_lo);

    float acc[8][4];
#pragma unroll
    for (int n = 0; n < 8; n++) {
#pragma unroll
        for (int j = 0; j < 4; j++) acc[n][j] = 0.0f;
    }

#pragma unroll
    for (int ks = 0; ks < 8; ks++) {
        const int k0 = ks * 16;
        const uint32_t aoff = (uint32_t)(aRow * SM_STRIDE + k0 + aCol) * 2;
        Frag4 ah, al;
        ldsm4(ah, xs_hi_b + aoff);
        ldsm4(al, xs_lo_b + aoff);

#pragma unroll
        for (int pl = 0; pl < 4; pl++) {
            const int p = wn * 4 + pl;
            const uint32_t boff =
                (uint32_t)((p * 16 + bRow) * SM_STRIDE + k0 + bCol) * 2;
            Frag4 bh, bl;
            ldsm4(bh, ws_hi_b + boff);
            ldsm4(bl, ws_lo_b + boff);

            float* c0 = acc[2 * pl];
            float* c1 = acc[2 * pl + 1];
            // alternate accumulators for ILP on the HMMA RAW chains
            mma16816(c0, ah, bh.r[0], bh.r[1]);
            mma16816(c1, ah, bh.r[2], bh.r[3]);
            mma16816(c0, ah, bl.r[0], bl.r[1]);
            mma16816(c1, ah, bl.r[2], bl.r[3]);
            mma16816(c0, al, bh.r[0], bh.r[1]);
            mma16816(c1, al, bh.r[2], bh.r[3]);
        }
    }

    // Epilogue: g_y = dinv*xlin ; out = dinv^2*xlin + b
    const int gid  = lane >> 2;
    const int tig  = lane & 3;
    const int row0 = m0 + wm * 16 + gid;
    const int row1 = row0 + 8;
    float di0 = 0.0f;
    float di1 = 0.0f;
    if (row0 < N_NODES) di0 = g_dinv[row0];
    if (row1 < N_NODES) di1 = g_dinv[row1];

#pragma unroll
    for (int ntl = 0; ntl < 8; ntl++) {
        int nt = wn * 8 + ntl;
        int n  = nt * 8 + tig * 2;
        float b0 = b[n];
        float b1 = b[n + 1];
        if (row0 < N_NODES) {
            float y0 = acc[ntl][0] * di0;
            float y1 = acc[ntl][1] * di0;
            *(float2*)(g_y + (size_t)row0 * D + n) = make_float2(y0, y1);
            float2 o;
            o.x = y0 * di0 + b0;
            o.y = y1 * di0 + b1;
            *(float2*)(out + (size_t)row0 * D + n) = o;
        }
        if (row1 < N_NODES) {
            float y0 = acc[ntl][2] * di1;
            float y1 = acc[ntl][3] * di1;
            *(float2*)(g_y + (size_t)row1 * D + n) = make_float2(y0, y1);
            float2 o;
            o.x = y0 * di1 + b0;
            o.y = y1 * di1 + b1;
            *(float2*)(out + (size_t)row1 * D + n) = o;
        }
    }
}

// ---------------------------------------------------------------------------
// Edge scatter: one warp per edge; lane handles a float4. y is pre-scaled by
// dinv[src], so msg = dinv[dst] * y[src]. Vector reduction into out[dst].
__global__ __launch_bounds__(256)
void k_edges(const int* __restrict__ src, const int* __restrict__ dst,
             float* __restrict__ out) {
    int w    = (blockIdx.x * blockDim.x + threadIdx.x) >> 5;
    int lane = threadIdx.x & 31;
    if (w >= E_EDGES) return;

    int s = __ldg(src + w);
    int d = __ldg(dst + w);
    float nd = g_dinv[d];

    float4 v = *(const float4*)(g_y + (size_t)s * D + lane * 4);
    float* p = out + (size_t)d * D + lane * 4;
    asm volatile("red.global.add.v4.f32 [%0], {%1, %2, %3, %4};" ::
                 "l"(p),
                 "f"(v.x * nd), "f"(v.y * nd),
                 "f"(v.z * nd), "f"(v.w * nd)
                 : "memory");
}

// ---------------------------------------------------------------------------
extern "C" void kernel_launch(void* const* d_in, const int* in_sizes, int n_in,
                              void* d_out, int out_size) {
    const float* x  = (const float*)d_in[0];
    const int*   ei = (const int*)d_in[1];   // [2, E]: row 0 = src, row 1 = dst
    const float* W  = (const float*)d_in[2];
    const float* b  = (const float*)d_in[3];
    float* out = (float*)d_out;

    const int* src = ei;
    const int* dst = ei + E_EDGES;

    cudaFuncSetAttribute(k_gemm_mma,
                         cudaFuncAttributeMaxDynamicSharedMemorySize,
                         GEMM_SMEM_BYTES);

    k_prep_w<<<(D * D + 255) / 256, 256>>>(W);
    k_init_deg<<<(N_NODES + 255) / 256, 256>>>();
    k_count<<<(E_EDGES + 255) / 256, 256>>>(dst);
    k_dinv<<<(N_NODES + 255) / 256, 256>>>();
    k_gemm_mma<<<(N_NODES + 127) / 128, 512, GEMM_SMEM_BYTES>>>(x, b, out);

    long long total = (long long)E_EDGES * 32;
    int blocks = (int)((total + 255) / 256);
    k_edges<<<blocks, 256>>>(src, dst, out);
}

// round 13
// speedup vs baseline: 1.7794x; 1.0874x over previous
#include <cuda_runtime.h>
#include <cuda_fp16.h>
#include <cuda_bf16.h>
#include <cstdint>
#include <cstddef>

#define N_NODES 50000
#define E_EDGES 800000
#define D 128

// Scratch (device globals -- no allocation allowed)
__device__ float   g_deg[N_NODES];
__device__ float   g_dinv[N_NODES];
__device__ __half2 g_yh[(size_t)N_NODES * 64];   // y = dinv*xlin, fp16 packed
__device__ __half  g_Whi[D * D];
__device__ __half  g_Wlo[D * D];

// ---------------------------------------------------------------------------
// Fused setup: W split (i < D*D) + deg init to 1 (self-loop) for i < N.
__global__ void k_setup(const float* __restrict__ W) {
    int i = blockIdx.x * blockDim.x + threadIdx.x;
    if (i < D * D) {
        float v   = W[i];
        __half hi = __float2half_rn(v);
        __half lo = __float2half_rn(v - __half2float(hi));
        g_Whi[i] = hi;
        g_Wlo[i] = lo;
    }
    if (i < N_NODES) g_deg[i] = 1.0f;
}

__global__ void k_count(const int* __restrict__ dst) {
    int e = blockIdx.x * blockDim.x + threadIdx.x;
    if (e < E_EDGES) atomicAdd(&g_deg[dst[e]], 1.0f);
}

__global__ void k_dinv() {
    int i = blockIdx.x * blockDim.x + threadIdx.x;
    if (i < N_NODES) g_dinv[i] = rsqrtf(g_deg[i]);
}

// ---------------------------------------------------------------------------
// Tensor-core GEMM, fp16 2-term split (Markidis).
// BM=64 rows per CTA, 256 threads = 8 warps: wm = wid&3 (m-tile),
// wn = wid>>2 (n-half). K staged in 2 chunks of 64 -> smem 88KB -> 2 CTAs/SM.

#define W_STRIDE 136
#define X_STRIDE 72
#define WS_ARR (128 * W_STRIDE)            // halves
#define XS_ARR (64 * X_STRIDE)             // halves
#define GEMM_SMEM_BYTES ((2 * WS_ARR + 2 * XS_ARR) * 2)

struct Frag4 { uint32_t r[4]; };

__device__ __forceinline__ void ldsm4(Frag4& f, uint32_t addr) {
    asm volatile(
        "ldmatrix.sync.aligned.m8n8.x4.shared.b16 {%0,%1,%2,%3}, [%4];"
        : "=r"(f.r[0]), "=r"(f.r[1]), "=r"(f.r[2]), "=r"(f.r[3])
        : "r"(addr));
}

__device__ __forceinline__ void mma16816(float* c, const Frag4& a,
                                         uint32_t b0, uint32_t b1) {
    asm volatile(
        "mma.sync.aligned.m16n8k16.row.col.f32.f16.f16.f32 "
        "{%0,%1,%2,%3}, {%4,%5,%6,%7}, {%8,%9}, {%0,%1,%2,%3};"
        : "+f"(c[0]), "+f"(c[1]), "+f"(c[2]), "+f"(c[3])
        : "r"(a.r[0]), "r"(a.r[1]), "r"(a.r[2]), "r"(a.r[3]),
          "r"(b0), "r"(b1));
}

__device__ __forceinline__ uint32_t h2bits(__half a, __half b) {
    __half2 h = __halves2half2(a, b);
    return *(uint32_t*)&h;
}

__global__ __launch_bounds__(256)
void k_gemm_mma(const float* __restrict__ x, const float* __restrict__ b,
                float* __restrict__ out) {
    extern __shared__ __half sm[];
    __half* Ws_hi = sm;
    __half* Ws_lo = sm + WS_ARR;
    __half* Xs_hi = sm + 2 * WS_ARR;
    __half* Xs_lo = sm + 2 * WS_ARR + XS_ARR;

    const int tid  = threadIdx.x;
    const int lane = tid & 31;
    const int wid  = tid >> 5;        // 0..7
    const int wm   = wid & 3;         // m-tile -> rows wm*16..+15
    const int wn   = wid >> 2;        // n-half (0/1)
    const int m0   = blockIdx.x * 64;

    // ---- Stage W (full 128x128): vector copies from precomputed split ----
    for (int i = tid; i < 128 * 16; i += 256) {
        int r = i >> 4;
        int c = i & 15;              // uint4 index (8 halves each)
        *(uint4*)(Ws_hi + r * W_STRIDE + c * 8) =
            *(const uint4*)(g_Whi + r * 128 + c * 8);
        *(uint4*)(Ws_lo + r * W_STRIDE + c * 8) =
            *(const uint4*)(g_Wlo + r * 128 + c * 8);
    }

    // ldmatrix lane addressing (element offsets in halves)
    const int aRow = wm * 16 + (lane & 7) + ((lane >> 3) & 1) * 8;
    const int aCol = (lane >> 4) * 8;
    const int bRow = ((lane >> 4) & 1) * 8 + (lane & 7);
    const int bCol = ((lane >> 3) & 1) * 8;

    const uint32_t xs_hi_b = (uint32_t)__cvta_generic_to_shared(Xs_hi);
    const uint32_t xs_lo_b = (uint32_t)__cvta_generic_to_shared(Xs_lo);
    const uint32_t ws_hi_b = (uint32_t)__cvta_generic_to_shared(Ws_hi);
    const uint32_t ws_lo_b = (uint32_t)__cvta_generic_to_shared(Ws_lo);

    float acc[8][4];
#pragma unroll
    for (int n = 0; n < 8; n++) {
#pragma unroll
        for (int j = 0; j < 4; j++) acc[n][j] = 0.0f;
    }

#pragma unroll
    for (int kc = 0; kc < 2; kc++) {
        // ---- Stage X chunk: 64 rows x 64 cols (K window kc*64..+63) ----
        for (int i = tid; i < 64 * 16; i += 256) {
            int r  = i >> 4;
            int c4 = i & 15;          // float4 index within chunk
            int gr = m0 + r;
            float4 v = make_float4(0.f, 0.f, 0.f, 0.f);
            if (gr < N_NODES)
                v = *(const float4*)(x + (size_t)gr * D + kc * 64 + c4 * 4);

            __half h0 = __float2half_rn(v.x);
            __half h1 = __float2half_rn(v.y);
            __half h2 = __float2half_rn(v.z);
            __half h3 = __float2half_rn(v.w);
            __half l0 = __float2half_rn(v.x - __half2float(h0));
            __half l1 = __float2half_rn(v.y - __half2float(h1));
            __half l2 = __float2half_rn(v.z - __half2float(h2));
            __half l3 = __float2half_rn(v.w - __half2float(h3));

            uint2 hv, lv;
            hv.x = h2bits(h0, h1); hv.y = h2bits(h2, h3);
            lv.x = h2bits(l0, l1); lv.y = h2bits(l2, l3);
            *(uint2*)(Xs_hi + r * X_STRIDE + c4 * 4) = hv;
            *(uint2*)(Xs_lo + r * X_STRIDE + c4 * 4) = lv;
        }
        __syncthreads();

#pragma unroll
        for (int ks = 0; ks < 4; ks++) {
            const int k0l = ks * 16;            // within chunk
            const int kg  = kc * 64 + k0l;      // global K for W
            const uint32_t aoff = (uint32_t)(aRow * X_STRIDE + k0l + aCol) * 2;
            Frag4 ah, al;
            ldsm4(ah, xs_hi_b + aoff);
            ldsm4(al, xs_lo_b + aoff);

#pragma unroll
            for (int pl = 0; pl < 4; pl++) {
                const int p = wn * 4 + pl;
                const uint32_t boff =
                    (uint32_t)((p * 16 + bRow) * W_STRIDE + kg + bCol) * 2;
                Frag4 bh, bl;
                ldsm4(bh, ws_hi_b + boff);
                ldsm4(bl, ws_lo_b + boff);

                float* c0 = acc[2 * pl];
                float* c1 = acc[2 * pl + 1];
                mma16816(c0, ah, bh.r[0], bh.r[1]);
                mma16816(c1, ah, bh.r[2], bh.r[3]);
                mma16816(c0, ah, bl.r[0], bl.r[1]);
                mma16816(c1, ah, bl.r[2], bl.r[3]);
                mma16816(c0, al, bh.r[0], bh.r[1]);
                mma16816(c1, al, bh.r[2], bh.r[3]);
            }
        }
        __syncthreads();
    }

    // Epilogue: g_yh = fp16(dinv*xlin) ; out = dinv^2*xlin + b
    const int gid  = lane >> 2;
    const int tig  = lane & 3;
    const int row0 = m0 + wm * 16 + gid;
    const int row1 = row0 + 8;
    float di0 = 0.0f;
    float di1 = 0.0f;
    if (row0 < N_NODES) di0 = g_dinv[row0];
    if (row1 < N_NODES) di1 = g_dinv[row1];

#pragma unroll
    for (int ntl = 0; ntl < 8; ntl++) {
        int nt = wn * 8 + ntl;
        int n  = nt * 8 + tig * 2;
        float b0 = b[n];
        float b1 = b[n + 1];
        if (row0 < N_NODES) {
            float y0 = acc[ntl][0] * di0;
            float y1 = acc[ntl][1] * di0;
            g_yh[(size_t)row0 * 64 + nt * 4 + tig] = __floats2half2_rn(y0, y1);
            float2 o;
            o.x = y0 * di0 + b0;
            o.y = y1 * di0 + b1;
            *(float2*)(out + (size_t)row0 * D + n) = o;
        }
        if (row1 < N_NODES) {
            float y0 = acc[ntl][2] * di1;
            float y1 = acc[ntl][3] * di1;
            g_yh[(size_t)row1 * 64 + nt * 4 + tig] = __floats2half2_rn(y0, y1);
            float2 o;
            o.x = y0 * di1 + b0;
            o.y = y1 * di1 + b1;
            *(float2*)(out + (size_t)row1 * D + n) = o;
        }
    }
}

// ---------------------------------------------------------------------------
// Edge scatter: one warp per edge; lane handles 4 floats (2 half2 = 8B gather).
// y pre-scaled by dinv[src]; msg = dinv[dst] * y[src]. Accumulate fp32.
__global__ __launch_bounds__(256)
void k_edges(const int* __restrict__ src, const int* __restrict__ dst,
             float* __restrict__ out) {
    int w    = (blockIdx.x * blockDim.x + threadIdx.x) >> 5;
    int lane = threadIdx.x & 31;
    if (w >= E_EDGES) return;

    int s = __ldg(src + w);
    int d = __ldg(dst + w);
    float nd = g_dinv[d];

    const __half2* yp = g_yh + (size_t)s * 64 + lane * 2;
    uint2 raw = *(const uint2*)yp;
    __half2 h0 = *(const __half2*)&raw.x;
    __half2 h1 = *(const __half2*)&raw.y;
    float2 f0 = __half22float2(h0);
    float2 f1 = __half22float2(h1);

    float* p = out + (size_t)d * D + lane * 4;
    asm volatile("red.global.add.v4.f32 [%0], {%1, %2, %3, %4};" ::
                 "l"(p),
                 "f"(f0.x * nd), "f"(f0.y * nd),
                 "f"(f1.x * nd), "f"(f1.y * nd)
                 : "memory");
}

// ---------------------------------------------------------------------------
extern "C" void kernel_launch(void* const* d_in, const int* in_sizes, int n_in,
                              void* d_out, int out_size) {
    const float* x  = (const float*)d_in[0];
    const int*   ei = (const int*)d_in[1];   // [2, E]: row 0 = src, row 1 = dst
    const float* W  = (const float*)d_in[2];
    const float* b  = (const float*)d_in[3];
    float* out = (float*)d_out;

    const int* src = ei;
    const int* dst = ei + E_EDGES;

    cudaFuncSetAttribute(k_gemm_mma,
                         cudaFuncAttributeMaxDynamicSharedMemorySize,
                         GEMM_SMEM_BYTES);

    k_setup<<<(N_NODES + 255) / 256, 256>>>(W);
    k_count<<<(E_EDGES + 255) / 256, 256>>>(dst);
    k_dinv<<<(N_NODES + 255) / 256, 256>>>();
    k_gemm_mma<<<(N_NODES + 63) / 64, 256, GEMM_SMEM_BYTES>>>(x, b, out);

    long long total = (long long)E_EDGES * 32;
    int blocks = (int)((total + 255) / 256);
    k_edges<<<blocks, 256>>>(src, dst, out);
}